// round 16
// baseline (speedup 1.0000x reference)
#include <cuda_runtime.h>
#include <cuda_fp16.h>

// CRF forward recursion — multiplicative exp2-domain, TWO batches per WARP
// (dual independent chains in one instruction stream; the E2h registers are
// shared, and each chain's latency gaps are filled by the other chain's
// HFMA2s). fp16 matvec (HFMA2, rt=2), fp32 control path, R8-verified
// exchange: p as half2 in warp-private double-buffered smem, ONE __syncwarp
// per (double-)step. E2h = fp16(exp2(trans*log2e - 8)), corrected by +8*T
// at the end; renorm shift d = lg2(max p over sampled tags {2,3,34,35}).

#define FULLMASK 0xffffffffu

__device__ __forceinline__ float ex2f_(float x){float r;asm("ex2.approx.f32 %0,%1;":"=f"(r):"f"(x));return r;}
__device__ __forceinline__ float lg2f_(float x){float r;asm("lg2.approx.f32 %0,%1;":"=f"(r):"f"(x));return r;}
// d.hi = convert(hi), d.lo = convert(lo), saturating to +/-65504 (no inf)
__device__ __forceinline__ unsigned f22h2sat_(float hi, float lo){
    unsigned r; asm("cvt.rn.satfinite.f16x2.f32 %0,%1,%2;":"=r"(r):"f"(hi),"f"(lo)); return r;
}

// Dual matvec: both batches' 64-prev reductions interleaved (shared E regs).
// Produces fp32 SA0,SA1 (batch A cols c0,c1) and SB0,SB1 (batch B).
#define MATVEC2(BUF)                                                    \
    {                                                                   \
        const uint4* __restrict__ ppA = (const uint4*)pbufA[BUF];       \
        const uint4* __restrict__ ppB = (const uint4*)pbufB[BUF];       \
        __half2 A0 = z2, A1 = z2, A2 = z2, A3 = z2;                     \
        __half2 Bb0 = z2, Bb1 = z2, Bb2 = z2, Bb3 = z2;                 \
        __half2 C0 = z2, C1 = z2, C2 = z2, C3 = z2;                     \
        __half2 D0 = z2, D1 = z2, D2 = z2, D3 = z2;                     \
        _Pragma("unroll")                                               \
        for (int k = 0; k < 8; k++) {                                   \
            const uint4 qa = ppA[k];          /* A: prevs 8k..8k+7 */   \
            const uint4 qb = ppB[k];          /* B: prevs 8k..8k+7 */   \
            const __half2 a0 = *(const __half2*)&qa.x;                  \
            const __half2 a1 = *(const __half2*)&qa.y;                  \
            const __half2 a2 = *(const __half2*)&qa.z;                  \
            const __half2 a3 = *(const __half2*)&qa.w;                  \
            const __half2 b0 = *(const __half2*)&qb.x;                  \
            const __half2 b1 = *(const __half2*)&qb.y;                  \
            const __half2 b2 = *(const __half2*)&qb.z;                  \
            const __half2 b3 = *(const __half2*)&qb.w;                  \
            A0  = __hfma2(a0, e0h[4*k+0], A0);                          \
            C0  = __hfma2(b0, e0h[4*k+0], C0);                          \
            Bb0 = __hfma2(a0, e1h[4*k+0], Bb0);                         \
            D0  = __hfma2(b0, e1h[4*k+0], D0);                          \
            A1  = __hfma2(a1, e0h[4*k+1], A1);                          \
            C1  = __hfma2(b1, e0h[4*k+1], C1);                          \
            Bb1 = __hfma2(a1, e1h[4*k+1], Bb1);                         \
            D1  = __hfma2(b1, e1h[4*k+1], D1);                          \
            A2  = __hfma2(a2, e0h[4*k+2], A2);                          \
            C2  = __hfma2(b2, e0h[4*k+2], C2);                          \
            Bb2 = __hfma2(a2, e1h[4*k+2], Bb2);                         \
            D2  = __hfma2(b2, e1h[4*k+2], D2);                          \
            A3  = __hfma2(a3, e0h[4*k+3], A3);                          \
            C3  = __hfma2(b3, e0h[4*k+3], C3);                          \
            Bb3 = __hfma2(a3, e1h[4*k+3], Bb3);                         \
            D3  = __hfma2(b3, e1h[4*k+3], D3);                          \
        }                                                               \
        const float2 fa0 = __half22float2(__hadd2(A0, A1));             \
        const float2 fa1 = __half22float2(__hadd2(A2, A3));             \
        const float2 fb0 = __half22float2(__hadd2(Bb0, Bb1));           \
        const float2 fb1 = __half22float2(__hadd2(Bb2, Bb3));           \
        const float2 fc0 = __half22float2(__hadd2(C0, C1));             \
        const float2 fc1 = __half22float2(__hadd2(C2, C3));             \
        const float2 fd0 = __half22float2(__hadd2(D0, D1));             \
        const float2 fd1 = __half22float2(__hadd2(D2, D3));             \
        SA0 = (fa0.x + fa0.y) + (fa1.x + fa1.y);                        \
        SA1 = (fb0.x + fb0.y) + (fb1.x + fb1.y);                        \
        SB0 = (fc0.x + fc0.y) + (fc1.x + fc1.y);                        \
        SB1 = (fd0.x + fd0.y) + (fd1.x + fd1.y);                        \
    }

// One double-step t>=1 (both batches advance one timestep).
#define STEP(BUF)                                                       \
    {                                                                   \
        float vA = fmaxf(pnfA0, pnfA1);                                 \
        float vB = fmaxf(pnfB0, pnfB1);                                 \
        vA = fmaxf(vA, __shfl_xor_sync(FULLMASK, vA, 16));              \
        vB = fmaxf(vB, __shfl_xor_sync(FULLMASK, vB, 16));              \
        const float pmA = __shfl_sync(FULLMASK, vA, 1);                 \
        const float pmB = __shfl_sync(FULLMASK, vB, 1);                 \
        const float dnA = lg2f_(pmA);                                   \
        const float dnB = lg2f_(pmB);                                   \
        MA += dnA;                                                      \
        MB += dnB;                                                      \
        float uA0 = ex2f_(fmaf(xqA0.x, LOG2E, -dnA));                   \
        float uA1 = ex2f_(fmaf(xqA0.y, LOG2E, -dnA));                   \
        float uB0 = ex2f_(fmaf(xqB0.x, LOG2E, -dnB));                   \
        float uB1 = ex2f_(fmaf(xqB0.y, LOG2E, -dnB));                   \
        if (c0 == 0) { uA0 = 0.0f; uB0 = 0.0f; }                        \
        xqA0 = xqA1;  xqA1 = *(const float2*)xpreA;                     \
        xqB0 = xqB1;  xqB1 = *(const float2*)xpreB;                     \
        xpreA += 64; if (xpreA > xlastA) xpreA = xlastA;                \
        xpreB += 64; if (xpreB > xlastB) xpreB = xlastB;                \
        float SA0, SA1, SB0, SB1;                                       \
        MATVEC2(BUF);                                                   \
        pnfA0 = SA0 * uA0;  pnfA1 = SA1 * uA1;                          \
        pnfB0 = SB0 * uB0;  pnfB1 = SB1 * uB1;                          \
        ((unsigned*)pbufA[(BUF) ^ 1])[lane] = f22h2sat_(pnfA1, pnfA0);  \
        ((unsigned*)pbufB[(BUF) ^ 1])[lane] = f22h2sat_(pnfB1, pnfB0);  \
        __syncwarp();                                                   \
    }

__global__ __launch_bounds__(32, 1)
void crf_forward_kernel(const float* __restrict__ X,
                        const float* __restrict__ trans,
                        float* __restrict__ out,
                        int B, int T)
{
    constexpr float LOG2E = 1.4426950408889634f;
    constexpr float LN2   = 0.6931471805599453f;
    constexpr float NEG2  = -10000.0f * 1.4426950408889634f;
    constexpr float SCALE = 8.0f;                 // E2 pre-scaled by 2^-8

    const int lane = threadIdx.x & 31;
    const int c0   = 2 * lane;
    const int c1   = c0 + 1;
    const int bA   = blockIdx.x * 2;
    int bB = bA + 1; if (bB >= B) bB = bA;        // defensive (B even here)

    // p exchange: per-batch double-buffered half2[32] (word l = tags 2l,2l+1)
    __shared__ __align__(16) __half2 pbufA[2][32];
    __shared__ __align__(16) __half2 pbufB[2][32];

    const __half2 z2 = __float2half2_rn(0.0f);

    // E2h[k] = fp16( exp2(trans[2k..2k+1][c] * log2e - SCALE) ) — SHARED by
    // both chains. Column 0 (tag 'B', trans masked -1e4) overridden to
    // exp2(-SCALE); the -1e4 is applied exactly via u[0]=0 per step and the
    // NEG2 constant in the epilogue. Row 1 (tag 'E', masked) underflows to
    // exactly 0 — matches the reference's shifted-exp underflow.
    __half2 e0h[32], e1h[32];
    const float escale = ex2f_(-SCALE);
#pragma unroll
    for (int k = 0; k < 32; k++) {
        const float t00 = trans[(2*k    ) * 64 + c0];
        const float t10 = trans[(2*k + 1) * 64 + c0];
        const float t01 = trans[(2*k    ) * 64 + c1];
        const float t11 = trans[(2*k + 1) * 64 + c1];
        const float f00 = (c0 == 0) ? escale : ex2f_(fmaf(t00, LOG2E, -SCALE));
        const float f10 = (c0 == 0) ? escale : ex2f_(fmaf(t10, LOG2E, -SCALE));
        e0h[k] = __floats2half2_rn(f00, f10);
        e1h[k] = __floats2half2_rn(ex2f_(fmaf(t01, LOG2E, -SCALE)),
                                   ex2f_(fmaf(t11, LOG2E, -SCALE)));
    }

    const float* __restrict__ xpA = X + (size_t)bA * T * 64 + c0;
    const float* __restrict__ xpB = X + (size_t)bB * T * 64 + c0;
    const float* xlastA = xpA + (size_t)(T - 1) * 64;
    const float* xlastB = xpB + (size_t)(T - 1) * 64;

    // ---- step 0 peeled analytically: p_0 one-hot -> p_1[c] = E2h[0][c]*u_0[c]
    const float2 xA0 = *(const float2*)xpA;
    const float2 xB0 = *(const float2*)xpB;
    const float e00 = __half2float(__low2half(e0h[0]));
    const float e01 = __half2float(__low2half(e1h[0]));
    float pnfA0 = (c0 == 0) ? 0.0f : e00 * ex2f_(xA0.x * LOG2E);
    float pnfA1 = e01 * ex2f_(xA0.y * LOG2E);
    float pnfB0 = (c0 == 0) ? 0.0f : e00 * ex2f_(xB0.x * LOG2E);
    float pnfB1 = e01 * ex2f_(xB0.y * LOG2E);
    ((unsigned*)pbufA[1])[lane] = f22h2sat_(pnfA1, pnfA0);
    ((unsigned*)pbufB[1])[lane] = f22h2sat_(pnfB1, pnfB0);
    __syncwarp();

    // x prefetch queues: xq0 = x_1, xq1 = x_2 (clamped for tiny T)
    const float* xA1p = xpA + 64;  if (xA1p > xlastA) xA1p = xlastA;
    const float* xA2p = xpA + 128; if (xA2p > xlastA) xA2p = xlastA;
    const float* xB1p = xpB + 64;  if (xB1p > xlastB) xB1p = xlastB;
    const float* xB2p = xpB + 128; if (xB2p > xlastB) xB2p = xlastB;
    float2 xqA0 = *(const float2*)xA1p;
    float2 xqA1 = *(const float2*)xA2p;
    float2 xqB0 = *(const float2*)xB1p;
    float2 xqB1 = *(const float2*)xB2p;
    const float* xpreA = xpA + 192; if (xpreA > xlastA) xpreA = xlastA;
    const float* xpreB = xpB + 192; if (xpreB > xlastB) xpreB = xlastB;

    float MA = 0.0f, MB = 0.0f;

    // ---- bodies t = 1 .. T-2, ping-pong unrolled x2
    const int npairs = (T - 2) >> 1;
#pragma unroll 1
    for (int it = 0; it < npairs; it++) {
        STEP(1);
        STEP(0);
    }
    int finbuf = 1;
    if ((T - 2) & 1) { STEP(1); finbuf = 0; }

    // ---- epilogue: S = p_{T-1} E2h;  alpha = (lg2 S + x*log2e + M + 8T)*ln2
    {
        float SA0, SA1, SB0, SB1;
        MATVEC2(finbuf);
        const float corrA = MA + SCALE * (float)T;
        const float corrB = MB + SCALE * (float)T;
        const float m0 = (c0 == 0) ? NEG2 : 0.0f;
        const float oA0 = (lg2f_(SA0) + xqA0.x * LOG2E + m0 + corrA) * LN2;
        const float oA1 = (lg2f_(SA1) + xqA0.y * LOG2E +      corrA) * LN2;
        const float oB0 = (lg2f_(SB0) + xqB0.x * LOG2E + m0 + corrB) * LN2;
        const float oB1 = (lg2f_(SB1) + xqB0.y * LOG2E +      corrB) * LN2;
        *(float2*)&out[(size_t)bA * 64 + c0] = make_float2(oA0, oA1);
        *(float2*)&out[(size_t)bB * 64 + c0] = make_float2(oB0, oB1);
    }
}

extern "C" void kernel_launch(void* const* d_in, const int* in_sizes, int n_in,
                              void* d_out, int out_size)
{
    const float* X     = (const float*)d_in[0];
    const float* trans = (const float*)d_in[1];
    float* out = (float*)d_out;

    const int B = out_size / 64;                  // 256
    const int T = in_sizes[0] / (B * 64);         // 512

    const int blocks = (B + 1) / 2;               // 1 warp per CTA, 2 batches
    crf_forward_kernel<<<blocks, 32>>>(X, trans, out, B, T);
}

// round 17
// speedup vs baseline: 1.0105x; 1.0105x over previous
#include <cuda_runtime.h>
#include <cuda_fp16.h>

// CRF forward recursion — multiplicative exp2-domain, TWO batches per WARP
// packed into the two HALVES of every half2 (batch-SIMD): smem word c =
// (p_A[c], p_B[c]); the matvec for column c is acc_c += word[j] *
// dup(E2[j][c]) via HFMA2 half-operand selectors on a SHARED packed E
// register file. One HFMA2 advances both batches -> all per-step overheads
// (LDS, sync, tail, renorm side chain) are amortized 2x. fp16 hot loop,
// fp32 control path. E2 pre-scaled by 2^-8 (corrected by +8*T at the end);
// per-batch renorm shift d = lg2(max p over sampled tags {2,3,34,35}).
// Double-buffered smem, ONE __syncwarp per (double-)step.

#define FULLMASK 0xffffffffu
typedef unsigned long long ull;

__device__ __forceinline__ float ex2f_(float x){float r;asm("ex2.approx.f32 %0,%1;":"=f"(r):"f"(x));return r;}
__device__ __forceinline__ float lg2f_(float x){float r;asm("lg2.approx.f32 %0,%1;":"=f"(r):"f"(x));return r;}
__device__ __forceinline__ unsigned h2bits_(__half2 h){ return *(unsigned*)&h; }
__device__ __forceinline__ __half2 bits2h_(unsigned u){ return *(__half2*)&u; }
// duplicate low/high half of a packed word (folds into HFMA2 .H0_H0/.H1_H1)
__device__ __forceinline__ __half2 dupL_(__half2 q){ return __half2half2(__low2half(q)); }
__device__ __forceinline__ __half2 dupH_(__half2 q){ return __half2half2(__high2half(q)); }

// Dual-batch matvec over all 64 prevs. S0OUT = (S_A[c0], S_B[c0]),
// S1OUT = (S_A[c1], S_B[c1]). 128 HFMA2 total (2 per prev word).
#define MATVEC2(BUF, S0OUT, S1OUT)                                      \
    {                                                                   \
        const uint4* __restrict__ pp = (const uint4*)pbuf[BUF];         \
        __half2 A0 = z2, A1 = z2, A2 = z2, A3 = z2;                     \
        __half2 C0 = z2, C1 = z2, C2 = z2, C3 = z2;                     \
        _Pragma("unroll")                                               \
        for (int k = 0; k < 16; k++) {                                  \
            const uint4 q = pp[k];          /* prev words 4k..4k+3 */   \
            const __half2 p0 = bits2h_(q.x);                            \
            const __half2 p1 = bits2h_(q.y);                            \
            const __half2 p2 = bits2h_(q.z);                            \
            const __half2 p3 = bits2h_(q.w);                            \
            A0 = __hfma2(p0, dupL_(ehc[4*k+0]), A0);                    \
            C0 = __hfma2(p0, dupH_(ehc[4*k+0]), C0);                    \
            A1 = __hfma2(p1, dupL_(ehc[4*k+1]), A1);                    \
            C1 = __hfma2(p1, dupH_(ehc[4*k+1]), C1);                    \
            A2 = __hfma2(p2, dupL_(ehc[4*k+2]), A2);                    \
            C2 = __hfma2(p2, dupH_(ehc[4*k+2]), C2);                    \
            A3 = __hfma2(p3, dupL_(ehc[4*k+3]), A3);                    \
            C3 = __hfma2(p3, dupH_(ehc[4*k+3]), C3);                    \
        }                                                               \
        S0OUT = __hadd2(__hadd2(A0, A1), __hadd2(A2, A3));              \
        S1OUT = __hadd2(__hadd2(C0, C1), __hadd2(C2, C3));              \
    }

// Publish p_{t+1}: words c0,c1 are adjacent -> one STS.64, then sync.
#define PUBLISH(BUF)                                                    \
    {                                                                   \
        ull wv;                                                         \
        asm("mov.b64 %0,{%1,%2};" : "=l"(wv)                            \
            : "r"(h2bits_(pn0)), "r"(h2bits_(pn1)));                    \
        ((ull*)pbuf[(BUF) ^ 1])[lane] = wv;                             \
        __syncwarp();                                                   \
    }

// One double-step t>=1: both batches advance one timestep.
#define STEP(BUF)                                                       \
    {                                                                   \
        __half2 v = __hmax2(pn0, pn1);   /* per-batch max of own cols */\
        unsigned vb = h2bits_(v);                                       \
        vb = h2bits_(__hmax2(bits2h_(vb),                               \
                             bits2h_(__shfl_xor_sync(FULLMASK, vb, 16))));\
        const unsigned pmb = __shfl_sync(FULLMASK, vb, 1);              \
        const float2 pmf = __half22float2(bits2h_(pmb));                \
        const float dnA = lg2f_(pmf.x);                                 \
        const float dnB = lg2f_(pmf.y);                                 \
        MA += dnA;  MB += dnB;                                          \
        float uA0 = ex2f_(fmaf(xqA0.x, LOG2E, -dnA));                   \
        const float uA1 = ex2f_(fmaf(xqA0.y, LOG2E, -dnA));             \
        float uB0 = ex2f_(fmaf(xqB0.x, LOG2E, -dnB));                   \
        const float uB1 = ex2f_(fmaf(xqB0.y, LOG2E, -dnB));             \
        if (c0 == 0) { uA0 = 0.0f; uB0 = 0.0f; }                        \
        const __half2 u0 = __floats2half2_rn(uA0, uB0);                 \
        const __half2 u1 = __floats2half2_rn(uA1, uB1);                 \
        xqA0 = xqA1;  xqA1 = *(const float2*)xpreA;                     \
        xqB0 = xqB1;  xqB1 = *(const float2*)xpreB;                     \
        xpreA += 64; if (xpreA > xlastA) xpreA = xlastA;                \
        xpreB += 64; if (xpreB > xlastB) xpreB = xlastB;                \
        __half2 S0, S1;                                                 \
        MATVEC2(BUF, S0, S1);                                           \
        pn0 = __hmin2(__hmul2(S0, u0), hclamp);                         \
        pn1 = __hmin2(__hmul2(S1, u1), hclamp);                         \
        PUBLISH(BUF);                                                   \
    }

__global__ __launch_bounds__(32, 1)
void crf_forward_kernel(const float* __restrict__ X,
                        const float* __restrict__ trans,
                        float* __restrict__ out,
                        int B, int T)
{
    constexpr float LOG2E = 1.4426950408889634f;
    constexpr float LN2   = 0.6931471805599453f;
    constexpr float NEG2  = -10000.0f * 1.4426950408889634f;
    constexpr float SCALE = 8.0f;                 // E2 pre-scaled by 2^-8

    const int lane = threadIdx.x & 31;
    const int c0   = 2 * lane;
    const int c1   = c0 + 1;
    const int bA   = blockIdx.x * 2;
    int bB = bA + 1; if (bB >= B) bB = bA;        // defensive (B even here)

    // p exchange: [double-buffer][64 words]; word c = (p_A[c], p_B[c])
    __shared__ __align__(16) __half2 pbuf[2][64];

    const __half2 z2     = __float2half2_rn(0.0f);
    const __half2 hclamp = __float2half2_rn(65504.0f);

    // ehc[j] = fp16( exp2(trans[j][{c0,c1}] * log2e - SCALE) ), columns packed
    // (shared by both batches; halves selected per column via dupL/dupH).
    // Column 0 (tag 'B', trans masked -1e4) overridden to exp2(-SCALE); the
    // -1e4 is applied exactly via u[0]=0 per step and the NEG2 constant in
    // the epilogue. Row 1 (tag 'E', masked) underflows to exactly 0 —
    // matching the reference's shifted-exp underflow.
    __half2 ehc[64];
    const float escale = ex2f_(-SCALE);
#pragma unroll
    for (int j = 0; j < 64; j++) {
        const float t0 = trans[j * 64 + c0];
        const float t1 = trans[j * 64 + c1];
        const float f0 = (c0 == 0) ? escale : ex2f_(fmaf(t0, LOG2E, -SCALE));
        const float f1 = ex2f_(fmaf(t1, LOG2E, -SCALE));
        ehc[j] = __floats2half2_rn(f0, f1);
    }

    const float* __restrict__ xpA = X + (size_t)bA * T * 64 + c0;
    const float* __restrict__ xpB = X + (size_t)bB * T * 64 + c0;
    const float* xlastA = xpA + (size_t)(T - 1) * 64;
    const float* xlastB = xpB + (size_t)(T - 1) * 64;

    // ---- step 0 peeled analytically: p_0 one-hot ->
    //      p_1[c] = E2[0][c] * u_0[c] per batch (masked at column 0).
    const float2 xA0 = *(const float2*)xpA;
    const float2 xB0 = *(const float2*)xpB;
    const float e00 = __half2float(__low2half(ehc[0]));   // E2[0][c0]
    const float e01 = __half2float(__high2half(ehc[0]));  // E2[0][c1]
    const float uA00 = (c0 == 0) ? 0.0f : ex2f_(xA0.x * LOG2E);
    const float uB00 = (c0 == 0) ? 0.0f : ex2f_(xB0.x * LOG2E);
    __half2 pn0 = __floats2half2_rn(e00 * uA00, e00 * uB00);  // (pA1[c0],pB1[c0])
    __half2 pn1 = __floats2half2_rn(e01 * ex2f_(xA0.y * LOG2E),
                                    e01 * ex2f_(xB0.y * LOG2E));
    PUBLISH(0);                                    // writes buffer 1

    // x prefetch queues: xq0 = x_1, xq1 = x_2 per batch (clamped)
    const float* xA1p = xpA + 64;  if (xA1p > xlastA) xA1p = xlastA;
    const float* xA2p = xpA + 128; if (xA2p > xlastA) xA2p = xlastA;
    const float* xB1p = xpB + 64;  if (xB1p > xlastB) xB1p = xlastB;
    const float* xB2p = xpB + 128; if (xB2p > xlastB) xB2p = xlastB;
    float2 xqA0 = *(const float2*)xA1p;
    float2 xqA1 = *(const float2*)xA2p;
    float2 xqB0 = *(const float2*)xB1p;
    float2 xqB1 = *(const float2*)xB2p;
    const float* xpreA = xpA + 192; if (xpreA > xlastA) xpreA = xlastA;
    const float* xpreB = xpB + 192; if (xpreB > xlastB) xpreB = xlastB;

    float MA = 0.0f, MB = 0.0f;

    // ---- bodies t = 1 .. T-2, ping-pong unrolled x2
    const int npairs = (T - 2) >> 1;
#pragma unroll 1
    for (int it = 0; it < npairs; it++) {
        STEP(1);
        STEP(0);
    }
    int finbuf = 1;
    if ((T - 2) & 1) { STEP(1); finbuf = 0; }

    // ---- epilogue: S = p_{T-1} E2;  alpha = (lg2 S + x*log2e + M + 8T)*ln2
    {
        __half2 S0, S1;
        MATVEC2(finbuf, S0, S1);
        const float2 s0 = __half22float2(S0);     // (S_A[c0], S_B[c0])
        const float2 s1 = __half22float2(S1);     // (S_A[c1], S_B[c1])
        const float corrA = MA + SCALE * (float)T;
        const float corrB = MB + SCALE * (float)T;
        const float m0 = (c0 == 0) ? NEG2 : 0.0f;
        const float oA0 = (lg2f_(s0.x) + xqA0.x * LOG2E + m0 + corrA) * LN2;
        const float oA1 = (lg2f_(s1.x) + xqA0.y * LOG2E +      corrA) * LN2;
        const float oB0 = (lg2f_(s0.y) + xqB0.x * LOG2E + m0 + corrB) * LN2;
        const float oB1 = (lg2f_(s1.y) + xqB0.y * LOG2E +      corrB) * LN2;
        *(float2*)&out[(size_t)bA * 64 + c0] = make_float2(oA0, oA1);
        *(float2*)&out[(size_t)bB * 64 + c0] = make_float2(oB0, oB1);
    }
}

extern "C" void kernel_launch(void* const* d_in, const int* in_sizes, int n_in,
                              void* d_out, int out_size)
{
    const float* X     = (const float*)d_in[0];
    const float* trans = (const float*)d_in[1];
    float* out = (float*)d_out;

    const int B = out_size / 64;                  // 256
    const int T = in_sizes[0] / (B * 64);         // 512

    const int blocks = (B + 1) / 2;               // 1 warp per CTA, 2 batches
    crf_forward_kernel<<<blocks, 32>>>(X, trans, out, B, T);
}